// round 16
// baseline (speedup 1.0000x reference)
#include <cuda_runtime.h>
#include <cuda_fp16.h>
#include <cstdint>

// ---------------- problem constants ----------------
#define BATCH   2
#define NPTS    110592            // 48^3
#define BN      (BATCH * NPTS)    // 221184
#define NF      256
#define NM      16
#define NCHUNK  576               // chunks per batch
#define CHUNK   192               // points per CTA (576 * 192 = 110592)
#define NPB     (CHUNK / 16)      // 12 point-blocks of 16
#define TWO_PI_F 6.283185307179586f
#define INV_SQRT_N 0.0030070286f  // 1/sqrt(110592)

#define NOUT       (BATCH * NF * NM)       // 8192 complex elements
#define OUT_FLOATS (NOUT * 2)              // 16384

// reduction tree: 576 = 36 * 16
#define R1_GROUPS  36
#define R1_CH      16

#define SZ_A   (BN * 16)
#define SZ_X   (BN * 3)
#define SZ_AW  (16 * 16)
#define SZ_XW  (3 * 256)

// SMEM (float units): aw[256] | xr[576] | x4[768] | astage[3072] | Ah(4096 halves)
#define SMF_AW  0
#define SMF_XR  256
#define SMF_X4  (256 + 576)              // 832 (16B aligned: 832*4=3328)
#define SMF_AS  (832 + 768)              // 1600
#define SMF_AH  (1600 + 3072)            // 4672
#define SMEM_BYTES ((4672 + 2048) * 4)   // 26880

// ---------------- device scratch (no allocation allowed) ----------------
__device__ float g_part[NCHUNK * OUT_FLOATS];     // per-chunk planar partials (37.7 MB)
__device__ float g_p2[R1_GROUPS * OUT_FLOATS];    // stage-1 partials (2.4 MB)

// ---------------- helpers ----------------
__device__ __forceinline__ uint32_t pack_h2(float lo, float hi) {
    uint32_t r;
    asm("cvt.rn.f16x2.f32 %0, %1, %2;" : "=r"(r) : "f"(hi), "f"(lo));
    return r;
}
__device__ __forceinline__ void mma_f16(float* d, const uint32_t* a, const uint32_t* b) {
    asm volatile(
        "mma.sync.aligned.m16n8k16.row.col.f32.f16.f16.f32 "
        "{%0,%1,%2,%3}, {%4,%5,%6,%7}, {%8,%9}, {%0,%1,%2,%3};"
        : "+f"(d[0]), "+f"(d[1]), "+f"(d[2]), "+f"(d[3])
        : "r"(a[0]), "r"(a[1]), "r"(a[2]), "r"(a[3]), "r"(b[0]), "r"(b[1]));
}

// ---------- fused kernel: stage + project + sincos + fp16 MMA ----------
// grid = (NCHUNK, BATCH), 256 threads; warp w covers f in [w*32, w*32+32).
// Coefficients UNscaled in fp16 (~N(0,1)); 1/sqrt(N) applied in epilogue.
// s_Ah layout: fp16 [m][p], row = 256 halves (128 u32 units), unit index
// swizzled u' = u ^ ((m&7)<<2)  -> B-operand LDS conflict-free.
__global__ void __launch_bounds__(256, 4) spectral_main(const float* __restrict__ a,
                                                        const float* __restrict__ x,
                                                        const float* __restrict__ aw,
                                                        const float* __restrict__ xw) {
    extern __shared__ float sm[];
    float*  s_aw = sm + SMF_AW;             // 16x16 row-major [i][m]
    float*  s_xr = sm + SMF_XR;             // 192 x 3 raw
    float4* s_x4 = (float4*)(sm + SMF_X4);  // 192 x float4 (padded)
    float*  s_as = sm + SMF_AS;             // 192 x 16 raw a staging
    __half* s_Ah = (__half*)(sm + SMF_AH);  // fp16 coefficients, swizzled [m][p]
    uint32_t* s_Ah32 = (uint32_t*)s_Ah;

    const int tid  = threadIdx.x;
    const int lane = tid & 31;
    const int warp = tid >> 5;
    const int b    = blockIdx.y;
    const int chunk = blockIdx.x;
    const size_t pbase = (size_t)(b * NPTS + chunk * CHUNK);

    // ---- stage: aw, raw a-chunk (12KB), raw x-chunk (2.25KB), coalesced ----
    s_aw[tid] = aw[tid];
    {
        const float4* ga = (const float4*)(a + pbase * 16);   // 768 float4
        float4* sa4 = (float4*)s_as;
#pragma unroll
        for (int i = 0; i < 3; ++i) sa4[tid + 256 * i] = ga[tid + 256 * i];
        const float4* gx = (const float4*)(x + pbase * 3);    // 144 float4
        float4* sx4 = (float4*)s_xr;
        if (tid < 144) sx4[tid] = gx[tid];
    }
    __syncthreads();

    if (tid < CHUNK) {
        // pad x to float4
        float r0 = s_xr[tid * 3 + 0], r1 = s_xr[tid * 3 + 1], r2 = s_xr[tid * 3 + 2];
        s_x4[tid] = make_float4(r0, r1, r2, 0.0f);

        // projection: o[m] = sum_i a[p][i]*aw[i][m]  (NO 1/sqrt(N) here)
        float ai[16];
#pragma unroll
        for (int i = 0; i < 16; ++i) ai[i] = s_as[tid * 16 + i];
        float o[16];
#pragma unroll
        for (int m = 0; m < 16; ++m) o[m] = 0.0f;
#pragma unroll
        for (int i = 0; i < 16; ++i)
#pragma unroll
            for (int m = 0; m < 16; ++m)
                o[m] = fmaf(ai[i], s_aw[i * 16 + m], o[m]);

        // fp16 store, swizzled: (m, p=tid)
        const int u  = tid >> 1;
        const int lo = tid & 1;
#pragma unroll
        for (int m = 0; m < 16; ++m) {
            int up = u ^ ((m & 7) << 2);
            s_Ah[m * 256 + up * 2 + lo] = __float2half_rn(o[m]);
        }
    }
    __syncthreads();

    // ---- per-thread frequency weights (2*pi folded), 4 f's per thread ----
    const int g  = lane >> 2;       // row within f-tile / m channel for B
    const int kp = lane & 3;        // k-slot
    const int fb = warp * 32 + g;
    float W[4][3];
#pragma unroll
    for (int j = 0; j < 4; ++j) {
        int f = fb + 8 * j;
        W[j][0] = TWO_PI_F * xw[f];
        W[j][1] = TWO_PI_F * xw[NF + f];
        W[j][2] = TWO_PI_F * xw[2 * NF + f];
    }

    float accR[2][2][4], accI[2][2][4];
#pragma unroll
    for (int i = 0; i < 2; ++i)
#pragma unroll
        for (int j = 0; j < 2; ++j)
#pragma unroll
            for (int k = 0; k < 4; ++k) { accR[i][j][k] = 0.0f; accI[i][j][k] = 0.0f; }

    const int sw = g << 2;          // B swizzle constant ((m&7)<<2, m0 = g)

    for (int pb = 0; pb < NPB; ++pb) {
        const int p0 = pb * 16 + 2 * kp;
        const int ub = pb * 8 + kp;

        // B fragments (fp16x2 pairs), conflict-free swizzled LDS
        uint32_t bm0[2] = { s_Ah32[g * 128 + (ub ^ sw)],
                            s_Ah32[g * 128 + ((ub + 4) ^ sw)] };
        uint32_t bm8[2] = { s_Ah32[(g + 8) * 128 + (ub ^ sw)],
                            s_Ah32[(g + 8) * 128 + ((ub + 4) ^ sw)] };

#pragma unroll
        for (int ft = 0; ft < 2; ++ft) {
            uint32_t fc[4], fs[4];
#pragma unroll
            for (int h = 0; h < 2; ++h) {
                float4 xa = s_x4[p0 + 8 * h];        // LDS.128 broadcast groups
                float4 xb = s_x4[p0 + 8 * h + 1];
#pragma unroll
                for (int r = 0; r < 2; ++r) {
                    const float* Wj = W[ft * 2 + r];
                    float pa = fmaf(xa.x, Wj[0], fmaf(xa.y, Wj[1], xa.z * Wj[2]));
                    float pc = fmaf(xb.x, Wj[0], fmaf(xb.y, Wj[1], xb.z * Wj[2]));
                    float ca, sa, cb, sb;
                    __sincosf(pa, &sa, &ca);
                    __sincosf(pc, &sb, &cb);
                    fc[r + 2 * h] = pack_h2(ca, cb);
                    fs[r + 2 * h] = pack_h2(sa, sb);
                }
            }
            mma_f16(accR[ft][0], fc, bm0);
            mma_f16(accR[ft][1], fc, bm8);
            mma_f16(accI[ft][0], fs, bm0);
            mma_f16(accI[ft][1], fs, bm8);
        }
    }

    // ---- epilogue: C-fragment -> planar per-chunk partials (scale by 1/sqrt(N)) ----
    float* basep = g_part + (size_t)chunk * OUT_FLOATS;
#pragma unroll
    for (int ft = 0; ft < 2; ++ft) {
#pragma unroll
        for (int mh = 0; mh < 2; ++mh) {
            const float* aR = accR[ft][mh];
            const float* aI = accI[ft][mh];
            int mcol = mh * 8 + 2 * kp;
#pragma unroll
            for (int rh = 0; rh < 2; ++rh) {
                int f = warp * 32 + ft * 16 + g + rh * 8;
                size_t o = (size_t)(b * NF + f) * NM + mcol;
                float2 vr = make_float2(aR[2 * rh] * INV_SQRT_N,
                                        aR[2 * rh + 1] * INV_SQRT_N);
                float2 vi = make_float2(-aI[2 * rh] * INV_SQRT_N,
                                        -aI[2 * rh + 1] * INV_SQRT_N);
                *(float2*)(basep + o) = vr;              // real plane
                *(float2*)(basep + NOUT + o) = vi;       // imag plane
            }
        }
    }
}

// ---------- reduce stage 1: sum 16 chunks per group ----------
__global__ void __launch_bounds__(256) reduce1_kernel(void) {
    int j = blockIdx.x * 256 + threadIdx.x;
    int c0 = blockIdx.y * R1_CH;
    float s = 0.0f;
#pragma unroll
    for (int c = 0; c < R1_CH; ++c)
        s += g_part[(size_t)(c0 + c) * OUT_FLOATS + j];
    g_p2[(size_t)blockIdx.y * OUT_FLOATS + j] = s;
}

// ---------- reduce stage 2: sum 36 groups, write planar output ----------
__global__ void __launch_bounds__(256) reduce2_kernel(float* __restrict__ out, int write_imag) {
    int j = blockIdx.x * 256 + threadIdx.x;
    float s = 0.0f;
#pragma unroll
    for (int g = 0; g < R1_GROUPS; ++g)
        s += g_p2[(size_t)g * OUT_FLOATS + j];
    if (j < NOUT) out[j] = s;
    else if (write_imag) out[j] = s;
}

extern "C" void kernel_launch(void* const* d_in, const int* in_sizes, int n_in,
                              void* d_out, int out_size) {
    const float* a  = nullptr;
    const float* x  = nullptr;
    const float* aw = nullptr;
    const float* xw = nullptr;
    for (int i = 0; i < n_in; ++i) {
        switch (in_sizes[i]) {
            case SZ_A:  a  = (const float*)d_in[i]; break;
            case SZ_X:  x  = (const float*)d_in[i]; break;
            case SZ_AW: aw = (const float*)d_in[i]; break;
            case SZ_XW: xw = (const float*)d_in[i]; break;
            default: break;
        }
    }
    float* out = (float*)d_out;
    int write_imag = (out_size >= OUT_FLOATS) ? 1 : 0;

    cudaFuncSetAttribute(spectral_main,
                         cudaFuncAttributeMaxDynamicSharedMemorySize, SMEM_BYTES);

    dim3 grid(NCHUNK, BATCH);
    spectral_main<<<grid, 256, SMEM_BYTES>>>(a, x, aw, xw);
    dim3 rg1(OUT_FLOATS / 256, R1_GROUPS);
    reduce1_kernel<<<rg1, 256>>>();
    reduce2_kernel<<<OUT_FLOATS / 256, 256>>>(out, write_imag);
}